// round 12
// baseline (speedup 1.0000x reference)
#include <cuda_runtime.h>
#include <cstdint>

// Problem constants
#define Bz 8
#define Tz 1024
#define Dz 1024
#define Qz 8
#define Kz 4096
#define dz 128
#define Mz (Bz*Tz)               // 8192 rows
#define OUT_ELEMS (Mz*Dz)        // 8388608
#define IDX_ELEMS (Mz*Qz)        // 65536
#define NQ IDX_ELEMS

#define CAPG 8                   // slots per (query, tx-group); 16 groups -> 128

// Scratch (device globals: allocation-free rule)
__device__ float    g_xn[(size_t)Mz*Dz];     // fp32 normed x (exact rescore)
__device__ float    g_hc2[Qz*Kz];            // 0.5*||c||^2 fp32
__device__ float    g_xq2[NQ];               // ||x_{m,q}||^2 per query
__device__ unsigned g_maxx_b, g_maxc_b, g_c2max_b;   // float-bit maxima
__device__ int      g_idx[NQ];
__device__ int      g_cnt[(size_t)NQ*16];
__device__ int      g_cand[(size_t)NQ*128];
// int8 operands packed 4-per-int32
__device__ int g_x8[(size_t)64*8*4096];      // [mtile][q][kq 32][row 128]
__device__ int g_c8[(size_t)8*32*32*192];    // [q][chunk][kq 32][col-perm 192]

static __device__ __forceinline__ void cp16s(uint32_t s, const void* g){
    asm volatile("cp.async.cg.shared.global [%0], [%1], 16;" :: "r"(s), "l"(g));
}

// ---------------- Kernel 1: input rmsnorm + per-query norms + max|x| --------
__global__ void rmsnorm_in_kernel(const float* __restrict__ x,
                                  const float* __restrict__ w){
    int m = blockIdx.x, t = threadIdx.x;
    float4 v = reinterpret_cast<const float4*>(x)[(size_t)m*256 + t];
    float ss = v.x*v.x + v.y*v.y + v.z*v.z + v.w*v.w;
    __shared__ float sred[8];
    __shared__ float s_scale;
    #pragma unroll
    for (int o = 16; o > 0; o >>= 1) ss += __shfl_xor_sync(0xffffffffu, ss, o);
    if ((t & 31) == 0) sred[t >> 5] = ss;
    __syncthreads();
    if (t < 8){
        float s2 = sred[t];
        #pragma unroll
        for (int o = 4; o > 0; o >>= 1) s2 += __shfl_xor_sync(0xffu, s2, o);
        if (t == 0){
            float mean = s2 * (1.0f/1024.0f) + 1e-5f;
            float r = rsqrtf(mean);
            r = r * (1.5f - 0.5f*mean*r*r);
            s_scale = r;
        }
    }
    __syncthreads();
    float sc = s_scale;
    float4 wv = reinterpret_cast<const float4*>(w)[t];
    float4 o4 = make_float4(v.x*sc*wv.x, v.y*sc*wv.y, v.z*sc*wv.z, v.w*sc*wv.w);
    reinterpret_cast<float4*>(g_xn)[(size_t)m*256 + t] = o4;

    // per-(m,q) subnorm + block max|xn|
    float s2q = o4.x*o4.x + o4.y*o4.y + o4.z*o4.z + o4.w*o4.w;
    float mx  = fmaxf(fmaxf(fabsf(o4.x), fabsf(o4.y)), fmaxf(fabsf(o4.z), fabsf(o4.w)));
    #pragma unroll
    for (int o = 16; o > 0; o >>= 1){
        s2q += __shfl_xor_sync(0xffffffffu, s2q, o);
        mx = fmaxf(mx, __shfl_xor_sync(0xffffffffu, mx, o));
    }
    if ((t & 31) == 0){
        g_xq2[m*8 + (t >> 5)] = s2q;
        atomicMax(&g_maxx_b, __float_as_uint(mx));
    }
}

// ---------------- Kernel 2: hc2 + codebook maxima ----------------
__global__ void hc2_kernel(const float* __restrict__ cb){
    int code = blockIdx.x*8 + (threadIdx.x >> 5);
    int lane = threadIdx.x & 31;
    float4 c = reinterpret_cast<const float4*>(cb)[(size_t)code*32 + lane];
    float s = c.x*c.x + c.y*c.y + c.z*c.z + c.w*c.w;
    float mx = fmaxf(fmaxf(fabsf(c.x), fabsf(c.y)), fmaxf(fabsf(c.z), fabsf(c.w)));
    #pragma unroll
    for (int o = 16; o > 0; o >>= 1){
        s += __shfl_xor_sync(0xffffffffu, s, o);
        mx = fmaxf(mx, __shfl_xor_sync(0xffffffffu, mx, o));
    }
    if (lane == 0){
        g_hc2[code] = 0.5f*s;
        atomicMax(&g_c2max_b, __float_as_uint(s));
        atomicMax(&g_maxc_b, __float_as_uint(mx));
    }
}

// ---------------- Kernel 3: quantize x to int8 (transposed tile layout) -----
__global__ void quantx_kernel(){
    int m = blockIdx.x, t = threadIdx.x;
    float Sx = 127.0f / __uint_as_float(g_maxx_b);
    float4 v = reinterpret_cast<const float4*>(g_xn)[(size_t)m*256 + t];
    int i0 = __float2int_rn(v.x*Sx), i1 = __float2int_rn(v.y*Sx);
    int i2 = __float2int_rn(v.z*Sx), i3 = __float2int_rn(v.w*Sx);
    int p = (i0 & 0xff) | ((i1 & 0xff) << 8) | ((i2 & 0xff) << 16) | ((i3 & 0xff) << 24);
    int q = t >> 5, kq = t & 31, tile = m >> 7, row = m & 127;
    g_x8[(size_t)((tile*8 + q)*32 + kq)*128 + row] = p;
}

// ---------------- Kernel 4: quantize codebook (permuted col layout) ---------
__global__ void quantc_kernel(const float* __restrict__ cb){
    int t = threadIdx.x;
    int code = blockIdx.x*8 + (t >> 5);
    int kq = t & 31;
    float Sc = 127.0f / __uint_as_float(g_maxc_b);
    float4 c = reinterpret_cast<const float4*>(cb)[(size_t)code*32 + kq];
    int i0 = __float2int_rn(c.x*Sc), i1 = __float2int_rn(c.y*Sc);
    int i2 = __float2int_rn(c.z*Sc), i3 = __float2int_rn(c.w*Sc);
    int p = (i0 & 0xff) | ((i1 & 0xff) << 8) | ((i2 & 0xff) << 16) | ((i3 & 0xff) << 24);
    int q = code >> 12, n = code & 4095;
    int ch = n >> 7, col = n & 127;
    int pos = 12*(col >> 3) + (col & 7);
    g_c8[(size_t)((q*32 + ch)*32 + kq)*192 + pos] = p;
}

// ---------------- Kernel 5: DP4A screen + candidate collection ----------------
// Block (mtile, q): 256 thr, 8 warps. Warp: rows w*16 + tyw*8 + {0..7}; cols 8tx+{0..7}.
// 32 chunks of 128 codes, kq loop 32 (4 k each). acc int, score = rs*acc - hc2.
#define SM_A   0u
#define SM_B0  16896u
#define SM_B1  41472u
#define SM_HC  66048u
#define SMEM_SCREEN 82432

__global__ void __launch_bounds__(256, 2)
screen_kernel(){
    extern __shared__ __align__(16) unsigned char smem[];
    uint32_t sbase = (uint32_t)__cvta_generic_to_shared(smem);

    int tid = threadIdx.x, w = tid >> 5, L = tid & 31;
    int tx = L & 15, tyw = L >> 4;
    int mt = blockIdx.x, q = blockIdx.y, m0 = mt*128;
    int r0 = w*16 + tyw*8;

    // scales / margins
    float mxx = __uint_as_float(g_maxx_b);
    float mxc = __uint_as_float(g_maxc_b);
    float C2  = __uint_as_float(g_c2max_b);
    float hx = mxx * (1.0f/254.0f);
    float hc = mxc * (1.0f/254.0f);
    float rs = (mxx*mxc) * (1.0f/(127.0f*127.0f));
    float dc = 128.0f*hx*hc;

    // prologue cp.async: A (padded 132-stride), hc2, B chunk0
    const unsigned char* gA = (const unsigned char*)(g_x8 + (size_t)(mt*8 + q)*4096);
    #pragma unroll
    for (int i = 0; i < 4; ++i){
        int u = tid + i*256;           // 0..1023
        int kq = u >> 5, r4 = u & 31;
        cp16s(sbase + SM_A + (uint32_t)(kq*132 + r4*4)*4u, gA + (size_t)(kq*128 + r4*4)*4);
    }
    const unsigned char* gH = (const unsigned char*)(g_hc2 + q*Kz);
    #pragma unroll
    for (int i = 0; i < 4; ++i)
        cp16s(sbase + SM_HC + (uint32_t)(tid + i*256)*16u, gH + (size_t)(tid + i*256)*16);
    const unsigned char* gB0 = (const unsigned char*)(g_c8 + (size_t)(q*32)*32*192);
    #pragma unroll
    for (int i = 0; i < 6; ++i)
        cp16s(sbase + SM_B0 + (uint32_t)(tid + i*256)*16u, gB0 + (size_t)(tid + i*256)*16);
    asm volatile("cp.async.commit_group;");

    // per-row state
    float thr[8], mrg[8];
    int   cnt[8], gq[8];
    #pragma unroll
    for (int p = 0; p < 8; ++p){
        float X2 = g_xq2[(m0 + r0 + p)*8 + q];
        mrg[p] = dc + 16.0f*sqrtf((hx*hx*C2 + hc*hc*X2)*(1.0f/3.0f));
        thr[p] = -3.0e38f;
        cnt[p] = 0;
        gq[p]  = (m0 + r0 + p)*8 + q;
    }

    const float* hcs = (const float*)(smem + SM_HC);
    const int*   As  = (const int*)(smem + SM_A);

    for (int c = 0; c < 32; ++c){
        __syncthreads();               // all readers of buf[(c+1)&1] (iter c-1) done
        if (c + 1 < 32){
            const unsigned char* gB = (const unsigned char*)(g_c8 + (size_t)(q*32 + c + 1)*32*192);
            uint32_t dst = sbase + (((c+1) & 1) ? SM_B1 : SM_B0);
            #pragma unroll
            for (int i = 0; i < 6; ++i)
                cp16s(dst + (uint32_t)(tid + i*256)*16u, gB + (size_t)(tid + i*256)*16);
            asm volatile("cp.async.commit_group;");
            asm volatile("cp.async.wait_group 1;");
        } else {
            asm volatile("cp.async.wait_group 0;");
        }
        __syncthreads();               // B[c] visible

        int acc[8][8];
        #pragma unroll
        for (int p = 0; p < 8; ++p)
            #pragma unroll
            for (int j = 0; j < 8; ++j) acc[p][j] = 0;

        const int* Bc = (const int*)(smem + ((c & 1) ? SM_B1 : SM_B0));

        #pragma unroll 4
        for (int kq = 0; kq < 32; ++kq){
            int4 a0 = *reinterpret_cast<const int4*>(As + kq*132 + r0);
            int4 a1 = *reinterpret_cast<const int4*>(As + kq*132 + r0 + 4);
            int4 b0 = *reinterpret_cast<const int4*>(Bc + kq*192 + 12*tx);
            int4 b1 = *reinterpret_cast<const int4*>(Bc + kq*192 + 12*tx + 4);
            int a[8] = {a0.x,a0.y,a0.z,a0.w,a1.x,a1.y,a1.z,a1.w};
            int b[8] = {b0.x,b0.y,b0.z,b0.w,b1.x,b1.y,b1.z,b1.w};
            #pragma unroll
            for (int p = 0; p < 8; ++p)
                #pragma unroll
                for (int j = 0; j < 8; ++j)
                    acc[p][j] = __dp4a(a[p], b[j], acc[p][j]);
        }

        // share thresholds across the 16 tx lanes owning these rows (lag: safe)
        #pragma unroll
        for (int p = 0; p < 8; ++p){
            float tv = thr[p];
            tv = fmaxf(tv, __shfl_xor_sync(0xffffffffu, tv, 1));
            tv = fmaxf(tv, __shfl_xor_sync(0xffffffffu, tv, 2));
            tv = fmaxf(tv, __shfl_xor_sync(0xffffffffu, tv, 4));
            tv = fmaxf(tv, __shfl_xor_sync(0xffffffffu, tv, 8));
            thr[p] = tv;
        }

        // scan
        #pragma unroll
        for (int j = 0; j < 8; ++j){
            int n = c*128 + 8*tx + j;
            float hv = hcs[n];
            #pragma unroll
            for (int p = 0; p < 8; ++p){
                float s = fmaf((float)acc[p][j], rs, -hv);
                if (s > thr[p]){
                    if (cnt[p] < CAPG) g_cand[(size_t)gq[p]*128 + tx*CAPG + cnt[p]] = n;
                    cnt[p]++;
                    thr[p] = fmaxf(thr[p], s - mrg[p]);
                }
            }
        }
    }

    #pragma unroll
    for (int p = 0; p < 8; ++p)
        g_cnt[(size_t)gq[p]*16 + tx] = cnt[p];
}

// ---------------- Kernel 6: exact fp32 rescore of candidates ----------------
__global__ void resolve_kernel(const float* __restrict__ cb, float* __restrict__ tail){
    int gw = blockIdx.x*8 + (threadIdx.x >> 5);     // query id 0..65535
    int lane = threadIdx.x & 31;
    int m = gw >> 3, q = gw & 7;
    float4 xv = reinterpret_cast<const float4*>(g_xn + (size_t)m*Dz + q*dz)[lane];
    const float* hq = g_hc2 + q*Kz;
    const float4* cbq = reinterpret_cast<const float4*>(cb + (size_t)q*Kz*dz);
    float bv = -3.4e38f; int bi = 0;

    int cc[16];
    #pragma unroll
    for (int i = 0; i < 4; ++i){
        int4 c4 = *reinterpret_cast<const int4*>(g_cnt + (size_t)gw*16 + i*4);
        cc[4*i] = c4.x; cc[4*i+1] = c4.y; cc[4*i+2] = c4.z; cc[4*i+3] = c4.w;
    }
    bool ok = true;
    #pragma unroll
    for (int t = 0; t < 16; ++t) ok = ok && (cc[t] <= CAPG);

    if (ok){
        #pragma unroll 1
        for (int t = 0; t < 16; ++t){
            for (int i = 0; i < cc[t]; ++i){
                int n = g_cand[(size_t)gw*128 + t*CAPG + i];
                float4 cv = cbq[(size_t)n*32 + lane];
                float p = xv.x*cv.x + xv.y*cv.y + xv.z*cv.z + xv.w*cv.w;
                #pragma unroll
                for (int o = 16; o > 0; o >>= 1) p += __shfl_xor_sync(0xffffffffu, p, o);
                float s = p - hq[n];
                if (s > bv || (s == bv && n < bi)) { bv = s; bi = n; }
            }
        }
    } else {
        // overflow fallback: brute force all codes (rare)
        for (int n = 0; n < Kz; ++n){
            float4 cv = cbq[(size_t)n*32 + lane];
            float p = xv.x*cv.x + xv.y*cv.y + xv.z*cv.z + xv.w*cv.w;
            #pragma unroll
            for (int o = 16; o > 0; o >>= 1) p += __shfl_xor_sync(0xffffffffu, p, o);
            float s = p - hq[n];
            if (s > bv) { bv = s; bi = n; }
        }
    }
    if (lane == 0){
        g_idx[gw] = bi;
        if (tail) tail[gw] = (float)bi;
    }
}

// ---------------- Kernel 7: gather codes + output rmsnorm ----------------
__global__ void out_kernel(const float* __restrict__ cb,
                           const float* __restrict__ w,
                           float* __restrict__ out){
    int m = blockIdx.x, t = threadIdx.x;
    __shared__ int   sidx[8];
    __shared__ float s_scale;
    if (t < 8) sidx[t] = g_idx[m*Qz + t];
    __syncthreads();
    if (t < 8){
        float p = g_hc2[t*Kz + sidx[t]];
        #pragma unroll
        for (int o = 4; o > 0; o >>= 1) p += __shfl_xor_sync(0xffu, p, o);
        if (t == 0){
            float mean = (2.0f*p) * (1.0f/1024.0f) + 1e-5f;
            float r = rsqrtf(mean);
            r = r * (1.5f - 0.5f*mean*r*r);
            s_scale = r;
        }
    }
    __syncthreads();
    int q = t >> 5, lane = t & 31;
    float4 c = reinterpret_cast<const float4*>(cb)[((size_t)q*Kz + sidx[q])*32 + lane];
    float sc = s_scale;
    float4 wv = reinterpret_cast<const float4*>(w)[t];
    reinterpret_cast<float4*>(out)[(size_t)m*256 + t] =
        make_float4(c.x*sc*wv.x, c.y*sc*wv.y, c.z*sc*wv.z, c.w*sc*wv.w);
}

// ---------------- Launch ----------------
extern "C" void kernel_launch(void* const* d_in, const int* in_sizes, int n_in,
                              void* d_out, int out_size){
    const float* x     = (const float*)d_in[0];
    const float* cb    = (const float*)d_in[1];
    const float* w_in  = (const float*)d_in[2];
    const float* w_out = (const float*)d_in[3];
    float* out = (float*)d_out;
    float* tail = (out_size >= OUT_ELEMS + IDX_ELEMS) ? (out + OUT_ELEMS) : nullptr;

    cudaFuncSetAttribute((const void*)screen_kernel,
                         cudaFuncAttributeMaxDynamicSharedMemorySize, SMEM_SCREEN);

    rmsnorm_in_kernel<<<Mz, 256>>>(x, w_in);
    hc2_kernel<<<(Qz*Kz)/8, 256>>>(cb);
    quantx_kernel<<<Mz, 256>>>();
    quantc_kernel<<<(Qz*Kz)/8, 256>>>(cb);
    screen_kernel<<<dim3(64, 8), 256, SMEM_SCREEN>>>();
    resolve_kernel<<<NQ/8, 256>>>(cb, tail);
    out_kernel<<<Mz, 256>>>(cb, w_out, out);
}

// round 14
// speedup vs baseline: 1.5055x; 1.5055x over previous
#include <cuda_runtime.h>
#include <cstdint>

// Problem constants
#define Bz 8
#define Tz 1024
#define Dz 1024
#define Qz 8
#define Kz 4096
#define dz 128
#define Mz (Bz*Tz)               // 8192 rows
#define OUT_ELEMS (Mz*Dz)        // 8388608
#define IDX_ELEMS (Mz*Qz)        // 65536

// Scratch (device globals: allocation-free rule)
__device__ float  g_xn[(size_t)Mz*Dz];        // rmsnorm'd input, 32MB
__device__ float  g_hc2[Qz*Kz];               // 0.5 * ||code||^2
__device__ float2 g_pb[(size_t)Mz*Qz*4];      // per-quarter partial (val, idx-bits)

// ---- f32x2 packed helpers (sm_103a FFMA2) ----
static __device__ __forceinline__ unsigned long long pack2(float v){
    unsigned long long r; unsigned u = __float_as_uint(v);
    asm("mov.b64 %0, {%1, %1};" : "=l"(r) : "r"(u));
    return r;
}
static __device__ __forceinline__ void ffma2(unsigned long long& d,
                                             unsigned long long a,
                                             unsigned long long b){
    asm("fma.rn.f32x2 %0, %1, %2, %0;" : "+l"(d) : "l"(a), "l"(b));
}
static __device__ __forceinline__ float2 unpack2(unsigned long long v){
    unsigned lo, hi;
    asm("mov.b64 {%0, %1}, %2;" : "=r"(lo), "=r"(hi) : "l"(v));
    return make_float2(__uint_as_float(lo), __uint_as_float(hi));
}

// ---------------- Kernel 1: fused input rmsnorm + hc2 ----------------
// blocks [0, 8192): rmsnorm row m = blockIdx.x
// blocks [8192, 12288): 0.5*||code||^2 for codes (blockIdx.x-8192)*8 + warp
__global__ void prep_kernel(const float* __restrict__ x,
                            const float* __restrict__ w,
                            const float* __restrict__ cb){
    int b = blockIdx.x, t = threadIdx.x;
    if (b < Mz){
        int m = b;
        float4 v = reinterpret_cast<const float4*>(x)[(size_t)m*256 + t];
        float ss = v.x*v.x + v.y*v.y + v.z*v.z + v.w*v.w;
        __shared__ float sred[8];
        __shared__ float s_scale;
        #pragma unroll
        for (int o = 16; o > 0; o >>= 1) ss += __shfl_xor_sync(0xffffffffu, ss, o);
        if ((t & 31) == 0) sred[t >> 5] = ss;
        __syncthreads();
        if (t < 8){
            float s2 = sred[t];
            #pragma unroll
            for (int o = 4; o > 0; o >>= 1) s2 += __shfl_xor_sync(0xffu, s2, o);
            if (t == 0){
                float mean = s2 * (1.0f/1024.0f) + 1e-5f;
                float r = rsqrtf(mean);
                r = r * (1.5f - 0.5f*mean*r*r);   // one Newton step
                s_scale = r;
            }
        }
        __syncthreads();
        float sc = s_scale;
        float4 wv = reinterpret_cast<const float4*>(w)[t];
        float4 o4 = make_float4(v.x*sc*wv.x, v.y*sc*wv.y, v.z*sc*wv.z, v.w*sc*wv.w);
        reinterpret_cast<float4*>(g_xn)[(size_t)m*256 + t] = o4;
    } else {
        int code = (b - Mz)*8 + (t >> 5);
        int lane = t & 31;
        float4 c = reinterpret_cast<const float4*>(cb)[(size_t)code*32 + lane];
        float s = c.x*c.x + c.y*c.y + c.z*c.z + c.w*c.w;
        #pragma unroll
        for (int o = 16; o > 0; o >>= 1) s += __shfl_xor_sync(0xffffffffu, s, o);
        if (lane == 0) g_hc2[code] = 0.5f*s;
    }
}

// ---------------- Kernel 2: fused GEMM + argmax(xc - 0.5c2), col-quartered ----
// Block = (128-row mtile, 1024-col quarter, q): blockIdx.x = mt*4 + qt.
// 2048 tasks -> 7 waves on 296 slots. Microkernel: 8x8 f32x2 outer product,
// broadcast A, reg-staged double-buffered B. Epilogue: scalar FMNMX max-tree +
// conditional rescan (first-match ascending == strict-> lowest-idx semantics).
#define SA   132                   // As row-dim stride (words)
#define BSTR 192                   // B k-row stride (words); 16 groups * 12
#define SMEM_ARGMIN (128*SA*4 + 2*16*BSTR*4)   // 67584 + 24576 = 92160

static __device__ __forceinline__ int bcol(int c){ return 12*(c>>3) + (c&7); }

__global__ void __launch_bounds__(256, 2)
argmin_kernel(const float* __restrict__ cb){
    extern __shared__ float sm[];
    float* As = sm;
    float* B0 = sm + 128*SA;
    float* B1 = B0 + 16*BSTR;

    int tid = threadIdx.x;
    int tx = tid & 15, ty = tid >> 4;
    int q  = blockIdx.y;
    int bx = blockIdx.x;
    int mt = bx >> 2, qt = bx & 3;
    int m0 = mt*128;
    int qb = qt*1024;                                  // column-quarter base

    const float* xq  = g_xn + (size_t)m0*Dz + q*dz;
    const float* cbq = cb + (size_t)q*Kz*dz + (size_t)qb*dz;
    const float* hcq = g_hc2 + q*Kz + qb;

    // ---- A tile: 128 rows x 128 k, transposed As[k][row]. One-time load.
    #pragma unroll
    for (int it = 0; it < 16; ++it){
        int u  = it*256 + tid;
        int kk = (u & 31) + ((u >> 10) << 5);
        int rg = (u >> 5) & 31;
        const float* p = xq + (size_t)(4*rg)*Dz + kk;
        float a0 = p[0], a1 = p[Dz], a2 = p[2*Dz], a3 = p[3*Dz];
        *reinterpret_cast<float4*>(&As[kk*SA + 4*rg]) = make_float4(a0,a1,a2,a3);
    }

    // per-thread B staging: 2 float4 per iteration (128 cols x 16 k / 256 thr)
    int pks0 = tid & 3,         pcol0 = tid >> 2;
    int pks1 = (256+tid) & 3,   pcol1 = (256+tid) >> 2;
    int bc0 = bcol(pcol0), bc1 = bcol(pcol1);

    // prologue: load + store B for iteration 0 into B0
    float4 pre0 = *reinterpret_cast<const float4*>(cbq + (size_t)pcol0*dz + 4*pks0);
    float4 pre1 = *reinterpret_cast<const float4*>(cbq + (size_t)pcol1*dz + 4*pks1);
    B0[(4*pks0+0)*BSTR + bc0] = pre0.x;  B0[(4*pks0+1)*BSTR + bc0] = pre0.y;
    B0[(4*pks0+2)*BSTR + bc0] = pre0.z;  B0[(4*pks0+3)*BSTR + bc0] = pre0.w;
    B0[(4*pks1+0)*BSTR + bc1] = pre1.x;  B0[(4*pks1+1)*BSTR + bc1] = pre1.y;
    B0[(4*pks1+2)*BSTR + bc1] = pre1.z;  B0[(4*pks1+3)*BSTR + bc1] = pre1.w;
    __syncthreads();

    unsigned long long acc[4][8];    // [row-pair][col]; rows 8*ty+2p, 8*ty+2p+1
    float bestv[8];
    int   besti[8];
    #pragma unroll
    for (int i = 0; i < 8; ++i){ bestv[i] = -3.4e38f; besti[i] = 0; }

    for (int it = 0; it < 64; ++it){            // it = chunk*8 + kc ; 8 chunks of 128 cols
        int c = it >> 3, kc = it & 7;

        // prefetch next B sub-tile into registers (hidden under compute)
        if (it + 1 < 64){
            int nc = (it+1) >> 3, nkc = (it+1) & 7;
            const float* bg = cbq + (size_t)nc*128*dz + nkc*16;
            pre0 = *reinterpret_cast<const float4*>(bg + (size_t)pcol0*dz + 4*pks0);
            pre1 = *reinterpret_cast<const float4*>(bg + (size_t)pcol1*dz + 4*pks1);
        }

        // chunk start: acc <- -0.5*||c||^2 (argmax form)
        if (kc == 0){
            float4 h0 = *reinterpret_cast<const float4*>(hcq + c*128 + 8*tx);
            float4 h1 = *reinterpret_cast<const float4*>(hcq + c*128 + 8*tx + 4);
            unsigned long long hp[8];
            hp[0]=pack2(-h0.x); hp[1]=pack2(-h0.y); hp[2]=pack2(-h0.z); hp[3]=pack2(-h0.w);
            hp[4]=pack2(-h1.x); hp[5]=pack2(-h1.y); hp[6]=pack2(-h1.z); hp[7]=pack2(-h1.w);
            #pragma unroll
            for (int p = 0; p < 4; ++p)
                #pragma unroll
                for (int j = 0; j < 8; ++j) acc[p][j] = hp[j];
        }

        const float* Bc = (it & 1) ? B1 : B0;
        const float* Ab = As + (kc*16)*SA + 8*ty;
        const float* Bb = Bc + 12*tx;

        #pragma unroll
        for (int k = 0; k < 16; ++k){
            ulonglong2 a0 = *reinterpret_cast<const ulonglong2*>(Ab + k*SA);      // rows 0-3
            ulonglong2 a1 = *reinterpret_cast<const ulonglong2*>(Ab + k*SA + 4);  // rows 4-7
            float4 b0 = *reinterpret_cast<const float4*>(Bb + k*BSTR);
            float4 b1 = *reinterpret_cast<const float4*>(Bb + k*BSTR + 4);
            unsigned long long bb0 = pack2(b0.x), bb1 = pack2(b0.y);
            unsigned long long bb2 = pack2(b0.z), bb3 = pack2(b0.w);
            unsigned long long bb4 = pack2(b1.x), bb5 = pack2(b1.y);
            unsigned long long bb6 = pack2(b1.z), bb7 = pack2(b1.w);
            ffma2(acc[0][0], a0.x, bb0); ffma2(acc[1][0], a0.y, bb0);
            ffma2(acc[2][0], a1.x, bb0); ffma2(acc[3][0], a1.y, bb0);
            ffma2(acc[0][1], a0.x, bb1); ffma2(acc[1][1], a0.y, bb1);
            ffma2(acc[2][1], a1.x, bb1); ffma2(acc[3][1], a1.y, bb1);
            ffma2(acc[0][2], a0.x, bb2); ffma2(acc[1][2], a0.y, bb2);
            ffma2(acc[2][2], a1.x, bb2); ffma2(acc[3][2], a1.y, bb2);
            ffma2(acc[0][3], a0.x, bb3); ffma2(acc[1][3], a0.y, bb3);
            ffma2(acc[2][3], a1.x, bb3); ffma2(acc[3][3], a1.y, bb3);
            ffma2(acc[0][4], a0.x, bb4); ffma2(acc[1][4], a0.y, bb4);
            ffma2(acc[2][4], a1.x, bb4); ffma2(acc[3][4], a1.y, bb4);
            ffma2(acc[0][5], a0.x, bb5); ffma2(acc[1][5], a0.y, bb5);
            ffma2(acc[2][5], a1.x, bb5); ffma2(acc[3][5], a1.y, bb5);
            ffma2(acc[0][6], a0.x, bb6); ffma2(acc[1][6], a0.y, bb6);
            ffma2(acc[2][6], a1.x, bb6); ffma2(acc[3][6], a1.y, bb6);
            ffma2(acc[0][7], a0.x, bb7); ffma2(acc[1][7], a0.y, bb7);
            ffma2(acc[2][7], a1.x, bb7); ffma2(acc[3][7], a1.y, bb7);
        }

        // drain staged regs into the other buffer
        if (it + 1 < 64){
            float* Bn = ((it+1) & 1) ? B1 : B0;
            Bn[(4*pks0+0)*BSTR + bc0] = pre0.x;  Bn[(4*pks0+1)*BSTR + bc0] = pre0.y;
            Bn[(4*pks0+2)*BSTR + bc0] = pre0.z;  Bn[(4*pks0+3)*BSTR + bc0] = pre0.w;
            Bn[(4*pks1+0)*BSTR + bc1] = pre1.x;  Bn[(4*pks1+1)*BSTR + bc1] = pre1.y;
            Bn[(4*pks1+2)*BSTR + bc1] = pre1.z;  Bn[(4*pks1+3)*BSTR + bc1] = pre1.w;
        }

        // chunk end: scalar FMNMX max-tree per row-pair; rescan only on
        // improvement. Ascending-j first-match + strict > across chunks ==
        // original "strict > keeps lowest idx" semantics, bit-exactly.
        if (kc == 7){
            int n0 = qb + c*128 + 8*tx;
            #pragma unroll
            for (int p = 0; p < 4; ++p){
                float2 v[8];
                #pragma unroll
                for (int j = 0; j < 8; ++j) v[j] = unpack2(acc[p][j]);
                float mx = fmaxf(fmaxf(fmaxf(v[0].x, v[1].x), fmaxf(v[2].x, v[3].x)),
                                 fmaxf(fmaxf(v[4].x, v[5].x), fmaxf(v[6].x, v[7].x)));
                float my = fmaxf(fmaxf(fmaxf(v[0].y, v[1].y), fmaxf(v[2].y, v[3].y)),
                                 fmaxf(fmaxf(v[4].y, v[5].y), fmaxf(v[6].y, v[7].y)));
                if (mx > bestv[2*p]){
                    bestv[2*p] = mx;
                    #pragma unroll 1
                    for (int j = 0; j < 8; ++j)
                        if (v[j].x == mx){ besti[2*p] = n0 + j; break; }
                }
                if (my > bestv[2*p+1]){
                    bestv[2*p+1] = my;
                    #pragma unroll 1
                    for (int j = 0; j < 8; ++j)
                        if (v[j].y == my){ besti[2*p+1] = n0 + j; break; }
                }
            }
        }
        __syncthreads();
    }

    // Cross-thread reduction: 16 tx candidates per row; max, tie -> lower idx
    float* rv = sm;                                    // 128*16 floats
    int*   ri = reinterpret_cast<int*>(sm + 128*16);   // 128*16 ints
    #pragma unroll
    for (int i = 0; i < 8; ++i){
        int row = 8*ty + i;
        rv[row*16 + tx] = bestv[i];
        ri[row*16 + tx] = besti[i];
    }
    __syncthreads();
    if (tid < 128){
        float bv = rv[tid*16]; int bi = ri[tid*16];
        #pragma unroll
        for (int t2 = 1; t2 < 16; ++t2){
            float v = rv[tid*16 + t2]; int id = ri[tid*16 + t2];
            if (v > bv || (v == bv && id < bi)) { bv = v; bi = id; }
        }
        int m = m0 + tid;
        g_pb[((size_t)m*Qz + q)*4 + qt] = make_float2(bv, __int_as_float(bi));
    }
}

// ---------------- Kernel 3: merge quarters + gather + output rmsnorm --------
__global__ void out_kernel(const float* __restrict__ cb,
                           const float* __restrict__ w,
                           float* __restrict__ out,
                           float* __restrict__ tail){
    int m = blockIdx.x, t = threadIdx.x;
    __shared__ int   sidx[8];
    __shared__ float s_scale;
    if (t < 8){
        // merge 4 column-quarter partials (quarters ascend -> tie to lower idx)
        const float2* pb = g_pb + ((size_t)m*Qz + t)*4;
        float2 p0 = pb[0];
        float bv = p0.x; int bi = __float_as_int(p0.y);
        #pragma unroll
        for (int qt = 1; qt < 4; ++qt){
            float2 p = pb[qt];
            int id = __float_as_int(p.y);
            if (p.x > bv || (p.x == bv && id < bi)) { bv = p.x; bi = id; }
        }
        sidx[t] = bi;
        if (tail) tail[m*Qz + t] = (float)bi;
    }
    __syncthreads();
    if (t < 8){
        float p = g_hc2[t*Kz + sidx[t]];
        #pragma unroll
        for (int o = 4; o > 0; o >>= 1) p += __shfl_xor_sync(0xffu, p, o);
        if (t == 0){
            float mean = (2.0f*p) * (1.0f/1024.0f) + 1e-5f;
            float r = rsqrtf(mean);
            r = r * (1.5f - 0.5f*mean*r*r);
            s_scale = r;
        }
    }
    __syncthreads();
    int q = t >> 5, lane = t & 31;
    float4 c = reinterpret_cast<const float4*>(cb)[((size_t)q*Kz + sidx[q])*32 + lane];
    float sc = s_scale;
    float4 wv = reinterpret_cast<const float4*>(w)[t];
    reinterpret_cast<float4*>(out)[(size_t)m*256 + t] =
        make_float4(c.x*sc*wv.x, c.y*sc*wv.y, c.z*sc*wv.z, c.w*sc*wv.w);
}

// ---------------- Launch ----------------
extern "C" void kernel_launch(void* const* d_in, const int* in_sizes, int n_in,
                              void* d_out, int out_size){
    const float* x     = (const float*)d_in[0];
    const float* cb    = (const float*)d_in[1];
    const float* w_in  = (const float*)d_in[2];
    const float* w_out = (const float*)d_in[3];
    float* out = (float*)d_out;
    float* tail = (out_size >= OUT_ELEMS + IDX_ELEMS) ? (out + OUT_ELEMS) : nullptr;

    cudaFuncSetAttribute((const void*)argmin_kernel,
                         cudaFuncAttributeMaxDynamicSharedMemorySize, SMEM_ARGMIN);

    prep_kernel<<<Mz + (Qz*Kz)/8, 256>>>(x, w_in, cb);
    argmin_kernel<<<dim3((Mz/128)*4, Qz), 256, SMEM_ARGMIN>>>(cb);
    out_kernel<<<Mz, 256>>>(cb, w_out, out, tail);
}

// round 15
// speedup vs baseline: 1.7037x; 1.1316x over previous
#include <cuda_runtime.h>
#include <cstdint>

// Problem constants
#define Bz 8
#define Tz 1024
#define Dz 1024
#define Qz 8
#define Kz 4096
#define dz 128
#define Mz (Bz*Tz)               // 8192 rows
#define OUT_ELEMS (Mz*Dz)        // 8388608
#define IDX_ELEMS (Mz*Qz)        // 65536

// Scratch (device globals: allocation-free rule)
__device__ float  g_xn[(size_t)Mz*Dz];        // rmsnorm'd input, 32MB
__device__ float  g_hc2[Qz*Kz];               // 0.5 * ||code||^2
__device__ float2 g_pb[(size_t)Mz*Qz*4];      // per-quarter partial (val, idx-bits)

// ---- f32x2 packed-FMA helpers (sm_103a FFMA2) ----
static __device__ __forceinline__ unsigned long long pack2(float v){
    unsigned long long r; unsigned u = __float_as_uint(v);
    asm("mov.b64 %0, {%1, %1};" : "=l"(r) : "r"(u));
    return r;
}
static __device__ __forceinline__ void ffma2(unsigned long long& d,
                                             unsigned long long a,
                                             unsigned long long b){
    asm("fma.rn.f32x2 %0, %1, %2, %0;" : "+l"(d) : "l"(a), "l"(b));
}
static __device__ __forceinline__ float2 unpack2(unsigned long long v){
    unsigned lo, hi;
    asm("mov.b64 {%0, %1}, %2;" : "=r"(lo), "=r"(hi) : "l"(v));
    return make_float2(__uint_as_float(lo), __uint_as_float(hi));
}

// ---------------- Kernel 1: fused input rmsnorm + hc2 ----------------
// blocks [0, 8192): rmsnorm row m = blockIdx.x
// blocks [8192, 12288): 0.5*||code||^2 for codes (blockIdx.x-8192)*8 + warp
__global__ void prep_kernel(const float* __restrict__ x,
                            const float* __restrict__ w,
                            const float* __restrict__ cb){
    int b = blockIdx.x, t = threadIdx.x;
    if (b < Mz){
        int m = b;
        float4 v = reinterpret_cast<const float4*>(x)[(size_t)m*256 + t];
        float ss = v.x*v.x + v.y*v.y + v.z*v.z + v.w*v.w;
        __shared__ float sred[8];
        __shared__ float s_scale;
        #pragma unroll
        for (int o = 16; o > 0; o >>= 1) ss += __shfl_xor_sync(0xffffffffu, ss, o);
        if ((t & 31) == 0) sred[t >> 5] = ss;
        __syncthreads();
        if (t < 8){
            float s2 = sred[t];
            #pragma unroll
            for (int o = 4; o > 0; o >>= 1) s2 += __shfl_xor_sync(0xffu, s2, o);
            if (t == 0){
                float mean = s2 * (1.0f/1024.0f) + 1e-5f;
                float r = rsqrtf(mean);
                r = r * (1.5f - 0.5f*mean*r*r);   // one Newton step
                s_scale = r;
            }
        }
        __syncthreads();
        float sc = s_scale;
        float4 wv = reinterpret_cast<const float4*>(w)[t];
        float4 o4 = make_float4(v.x*sc*wv.x, v.y*sc*wv.y, v.z*sc*wv.z, v.w*sc*wv.w);
        reinterpret_cast<float4*>(g_xn)[(size_t)m*256 + t] = o4;
    } else {
        int code = (b - Mz)*8 + (t >> 5);
        int lane = t & 31;
        float4 c = reinterpret_cast<const float4*>(cb)[(size_t)code*32 + lane];
        float s = c.x*c.x + c.y*c.y + c.z*c.z + c.w*c.w;
        #pragma unroll
        for (int o = 16; o > 0; o >>= 1) s += __shfl_xor_sync(0xffffffffu, s, o);
        if (lane == 0) g_hc2[code] = 0.5f*s;
    }
}

// ---------------- Kernel 2: fused GEMM + argmax(xc - 0.5c2), col-quartered ----
// Block = (128-row mtile, 1024-col quarter, q): blockIdx.x = mt*4 + qt.
// 2048 tasks -> 7 waves on 296 slots. Microkernel: 8x8 f32x2 outer product,
// broadcast A, reg-staged double-buffered B. Epilogue: predicated
// compare-update (branch-free; strict > keeps lowest idx).
#define SA   132                   // As row-dim stride (words); STS conflict-free
#define BSTR 192                   // B k-row stride (words); 16 groups * 12
#define SMEM_ARGMIN (128*SA*4 + 2*16*BSTR*4)   // 67584 + 24576 = 92160

static __device__ __forceinline__ int bcol(int c){ return 12*(c>>3) + (c&7); }

__global__ void __launch_bounds__(256, 2)
argmin_kernel(const float* __restrict__ cb){
    extern __shared__ float sm[];
    float* As = sm;
    float* B0 = sm + 128*SA;
    float* B1 = B0 + 16*BSTR;

    int tid = threadIdx.x;
    int tx = tid & 15, ty = tid >> 4;
    int q  = blockIdx.y;
    int bx = blockIdx.x;
    int mt = bx >> 2, qt = bx & 3;
    int m0 = mt*128;
    int qb = qt*1024;                                  // column-quarter base

    const float* xq  = g_xn + (size_t)m0*Dz + q*dz;
    const float* cbq = cb + (size_t)q*Kz*dz + (size_t)qb*dz;
    const float* hcq = g_hc2 + q*Kz + qb;

    // ---- A tile: 128 rows x 128 k, transposed As[k][row]. One-time load.
    #pragma unroll
    for (int it = 0; it < 16; ++it){
        int u  = it*256 + tid;
        int kk = (u & 31) + ((u >> 10) << 5);
        int rg = (u >> 5) & 31;
        const float* p = xq + (size_t)(4*rg)*Dz + kk;
        float a0 = p[0], a1 = p[Dz], a2 = p[2*Dz], a3 = p[3*Dz];
        *reinterpret_cast<float4*>(&As[kk*SA + 4*rg]) = make_float4(a0,a1,a2,a3);
    }

    // per-thread B staging: 2 float4 per iteration (128 cols x 16 k / 256 thr)
    int pks0 = tid & 3,         pcol0 = tid >> 2;
    int pks1 = (256+tid) & 3,   pcol1 = (256+tid) >> 2;
    int bc0 = bcol(pcol0), bc1 = bcol(pcol1);

    // prologue: load + store B for iteration 0 into B0
    float4 pre0 = *reinterpret_cast<const float4*>(cbq + (size_t)pcol0*dz + 4*pks0);
    float4 pre1 = *reinterpret_cast<const float4*>(cbq + (size_t)pcol1*dz + 4*pks1);
    B0[(4*pks0+0)*BSTR + bc0] = pre0.x;  B0[(4*pks0+1)*BSTR + bc0] = pre0.y;
    B0[(4*pks0+2)*BSTR + bc0] = pre0.z;  B0[(4*pks0+3)*BSTR + bc0] = pre0.w;
    B0[(4*pks1+0)*BSTR + bc1] = pre1.x;  B0[(4*pks1+1)*BSTR + bc1] = pre1.y;
    B0[(4*pks1+2)*BSTR + bc1] = pre1.z;  B0[(4*pks1+3)*BSTR + bc1] = pre1.w;
    __syncthreads();

    unsigned long long acc[4][8];    // [row-pair][col]; rows 8*ty+2p, 8*ty+2p+1
    float bestv[8];
    int   besti[8];
    #pragma unroll
    for (int i = 0; i < 8; ++i){ bestv[i] = -3.4e38f; besti[i] = 0; }

    for (int it = 0; it < 64; ++it){            // it = chunk*8 + kc ; 8 chunks of 128 cols
        int c = it >> 3, kc = it & 7;

        // prefetch next B sub-tile into registers (hidden under compute)
        if (it + 1 < 64){
            int nc = (it+1) >> 3, nkc = (it+1) & 7;
            const float* bg = cbq + (size_t)nc*128*dz + nkc*16;
            pre0 = *reinterpret_cast<const float4*>(bg + (size_t)pcol0*dz + 4*pks0);
            pre1 = *reinterpret_cast<const float4*>(bg + (size_t)pcol1*dz + 4*pks1);
        }

        // chunk start: acc <- -0.5*||c||^2 (argmax form)
        if (kc == 0){
            float4 h0 = *reinterpret_cast<const float4*>(hcq + c*128 + 8*tx);
            float4 h1 = *reinterpret_cast<const float4*>(hcq + c*128 + 8*tx + 4);
            unsigned long long hp[8];
            hp[0]=pack2(-h0.x); hp[1]=pack2(-h0.y); hp[2]=pack2(-h0.z); hp[3]=pack2(-h0.w);
            hp[4]=pack2(-h1.x); hp[5]=pack2(-h1.y); hp[6]=pack2(-h1.z); hp[7]=pack2(-h1.w);
            #pragma unroll
            for (int p = 0; p < 4; ++p)
                #pragma unroll
                for (int j = 0; j < 8; ++j) acc[p][j] = hp[j];
        }

        const float* Bc = (it & 1) ? B1 : B0;
        const float* Ab = As + (kc*16)*SA + 8*ty;
        const float* Bb = Bc + 12*tx;

        #pragma unroll
        for (int k = 0; k < 16; ++k){
            ulonglong2 a0 = *reinterpret_cast<const ulonglong2*>(Ab + k*SA);      // rows 0-3
            ulonglong2 a1 = *reinterpret_cast<const ulonglong2*>(Ab + k*SA + 4);  // rows 4-7
            float4 b0 = *reinterpret_cast<const float4*>(Bb + k*BSTR);
            float4 b1 = *reinterpret_cast<const float4*>(Bb + k*BSTR + 4);
            unsigned long long bb0 = pack2(b0.x), bb1 = pack2(b0.y);
            unsigned long long bb2 = pack2(b0.z), bb3 = pack2(b0.w);
            unsigned long long bb4 = pack2(b1.x), bb5 = pack2(b1.y);
            unsigned long long bb6 = pack2(b1.z), bb7 = pack2(b1.w);
            ffma2(acc[0][0], a0.x, bb0); ffma2(acc[1][0], a0.y, bb0);
            ffma2(acc[2][0], a1.x, bb0); ffma2(acc[3][0], a1.y, bb0);
            ffma2(acc[0][1], a0.x, bb1); ffma2(acc[1][1], a0.y, bb1);
            ffma2(acc[2][1], a1.x, bb1); ffma2(acc[3][1], a1.y, bb1);
            ffma2(acc[0][2], a0.x, bb2); ffma2(acc[1][2], a0.y, bb2);
            ffma2(acc[2][2], a1.x, bb2); ffma2(acc[3][2], a1.y, bb2);
            ffma2(acc[0][3], a0.x, bb3); ffma2(acc[1][3], a0.y, bb3);
            ffma2(acc[2][3], a1.x, bb3); ffma2(acc[3][3], a1.y, bb3);
            ffma2(acc[0][4], a0.x, bb4); ffma2(acc[1][4], a0.y, bb4);
            ffma2(acc[2][4], a1.x, bb4); ffma2(acc[3][4], a1.y, bb4);
            ffma2(acc[0][5], a0.x, bb5); ffma2(acc[1][5], a0.y, bb5);
            ffma2(acc[2][5], a1.x, bb5); ffma2(acc[3][5], a1.y, bb5);
            ffma2(acc[0][6], a0.x, bb6); ffma2(acc[1][6], a0.y, bb6);
            ffma2(acc[2][6], a1.x, bb6); ffma2(acc[3][6], a1.y, bb6);
            ffma2(acc[0][7], a0.x, bb7); ffma2(acc[1][7], a0.y, bb7);
            ffma2(acc[2][7], a1.x, bb7); ffma2(acc[3][7], a1.y, bb7);
        }

        // drain staged regs into the other buffer
        if (it + 1 < 64){
            float* Bn = ((it+1) & 1) ? B1 : B0;
            Bn[(4*pks0+0)*BSTR + bc0] = pre0.x;  Bn[(4*pks0+1)*BSTR + bc0] = pre0.y;
            Bn[(4*pks0+2)*BSTR + bc0] = pre0.z;  Bn[(4*pks0+3)*BSTR + bc0] = pre0.w;
            Bn[(4*pks1+0)*BSTR + bc1] = pre1.x;  Bn[(4*pks1+1)*BSTR + bc1] = pre1.y;
            Bn[(4*pks1+2)*BSTR + bc1] = pre1.z;  Bn[(4*pks1+3)*BSTR + bc1] = pre1.w;
        }

        // chunk end: fold acc into running argmax (strict > keeps lowest idx)
        if (kc == 7){
            int n0 = qb + c*128 + 8*tx;
            #pragma unroll
            for (int p = 0; p < 4; ++p)
                #pragma unroll
                for (int j = 0; j < 8; ++j){
                    float2 v = unpack2(acc[p][j]);
                    if (v.x > bestv[2*p])   { bestv[2*p]   = v.x; besti[2*p]   = n0 + j; }
                    if (v.y > bestv[2*p+1]) { bestv[2*p+1] = v.y; besti[2*p+1] = n0 + j; }
                }
        }
        __syncthreads();
    }

    // Cross-thread reduction: 16 tx candidates per row; max, tie -> lower idx
    float* rv = sm;                                    // 128*16 floats
    int*   ri = reinterpret_cast<int*>(sm + 128*16);   // 128*16 ints
    #pragma unroll
    for (int i = 0; i < 8; ++i){
        int row = 8*ty + i;
        rv[row*16 + tx] = bestv[i];
        ri[row*16 + tx] = besti[i];
    }
    __syncthreads();
    if (tid < 128){
        float bv = rv[tid*16]; int bi = ri[tid*16];
        #pragma unroll
        for (int t2 = 1; t2 < 16; ++t2){
            float v = rv[tid*16 + t2]; int id = ri[tid*16 + t2];
            if (v > bv || (v == bv && id < bi)) { bv = v; bi = id; }
        }
        int m = m0 + tid;
        g_pb[((size_t)m*Qz + q)*4 + qt] = make_float2(bv, __int_as_float(bi));
    }
}

// ---------------- Kernel 3: merge quarters + gather + output rmsnorm --------
__global__ void out_kernel(const float* __restrict__ cb,
                           const float* __restrict__ w,
                           float* __restrict__ out,
                           float* __restrict__ tail){
    int m = blockIdx.x, t = threadIdx.x;
    __shared__ int   sidx[8];
    __shared__ float s_scale;
    if (t < 8){
        // merge 4 column-quarter partials (quarters ascend -> tie to lower idx)
        const float2* pb = g_pb + ((size_t)m*Qz + t)*4;
        float2 p0 = pb[0];
        float bv = p0.x; int bi = __float_as_int(p0.y);
        #pragma unroll
        for (int qt = 1; qt < 4; ++qt){
            float2 p = pb[qt];
            int id = __float_as_int(p.y);
            if (p.x > bv || (p.x == bv && id < bi)) { bv = p.x; bi = id; }
        }
        sidx[t] = bi;
        if (tail) tail[m*Qz + t] = (float)bi;
    }
    __syncthreads();
    if (t < 8){
        float p = g_hc2[t*Kz + sidx[t]];
        #pragma unroll
        for (int o = 4; o > 0; o >>= 1) p += __shfl_xor_sync(0xffu, p, o);
        if (t == 0){
            float mean = (2.0f*p) * (1.0f/1024.0f) + 1e-5f;
            float r = rsqrtf(mean);
            r = r * (1.5f - 0.5f*mean*r*r);
            s_scale = r;
        }
    }
    __syncthreads();
    int q = t >> 5, lane = t & 31;
    float4 c = reinterpret_cast<const float4*>(cb)[((size_t)q*Kz + sidx[q])*32 + lane];
    float sc = s_scale;
    float4 wv = reinterpret_cast<const float4*>(w)[t];
    reinterpret_cast<float4*>(out)[(size_t)m*256 + t] =
        make_float4(c.x*sc*wv.x, c.y*sc*wv.y, c.z*sc*wv.z, c.w*sc*wv.w);
}

// ---------------- Launch ----------------
extern "C" void kernel_launch(void* const* d_in, const int* in_sizes, int n_in,
                              void* d_out, int out_size){
    const float* x     = (const float*)d_in[0];
    const float* cb    = (const float*)d_in[1];
    const float* w_in  = (const float*)d_in[2];
    const float* w_out = (const float*)d_in[3];
    float* out = (float*)d_out;
    float* tail = (out_size >= OUT_ELEMS + IDX_ELEMS) ? (out + OUT_ELEMS) : nullptr;

    cudaFuncSetAttribute((const void*)argmin_kernel,
                         cudaFuncAttributeMaxDynamicSharedMemorySize, SMEM_ARGMIN);

    prep_kernel<<<Mz + (Qz*Kz)/8, 256>>>(x, w_in, cb);
    argmin_kernel<<<dim3((Mz/128)*4, Qz), 256, SMEM_ARGMIN>>>(cb);
    out_kernel<<<Mz, 256>>>(cb, w_out, out, tail);
}